// round 15
// baseline (speedup 1.0000x reference)
#include <cuda_runtime.h>
#include <cuda_bf16.h>
#include <cuda_fp16.h>
#include <cstdint>

#define N_NODES_C 100000
#define N_EDGES_C 800000
#define HEADS 4
#define OUT_CH 32
#define IN_CH 128
#define HC 128            // HEADS*OUT_CH
#define EPS_F 1e-8f
#define TILE_M 64

// ---------------- device scratch (no allocs allowed) ----------------
__device__ __align__(16) uint32_t g_h16[(size_t)N_NODES_C * 64]; // h as half2 [N][64]
__device__ __align__(16) float g_as[N_NODES_C * HEADS];          // exp(0.01*alpha_s)
__device__ __align__(16) float g_den[N_NODES_C * HEADS];         // softmax denominators
__device__ __align__(16) int2  g_edges[N_EDGES_C];               // decoded (s,t)
__device__ int g_is64;                                           // edge index dtype flag
__device__ __align__(16) unsigned short g_Whi[HC * 128];         // W bf16 hi, swizzled
__device__ __align__(16) unsigned short g_Wlo[HC * 128];         // W bf16 lo, swizzled

__device__ __forceinline__ int ldidx(const void* p, long long i, int is64) {
    return is64 ? (int)((const long long*)p)[i] : ((const int*)p)[i];
}
__device__ __forceinline__ void red_v4(float* ptr, float4 v) {
    asm volatile("red.global.add.v4.f32 [%0], {%1,%2,%3,%4};"
                 :: "l"(ptr), "f"(v.x), "f"(v.y), "f"(v.z), "f"(v.w) : "memory");
}
__device__ __forceinline__ uint32_t smem_u32(const void* p) {
    uint32_t a;
    asm("{ .reg .u64 t; cvta.to.shared.u64 t, %1; cvt.u32.u64 %0, t; }" : "=r"(a) : "l"(p));
    return a;
}
__device__ __forceinline__ void cp_async16(uint32_t saddr, const void* gaddr) {
    asm volatile("cp.async.cg.shared.global [%0], [%1], 16;" :: "r"(saddr), "l"(gaddr));
}
__device__ __forceinline__ void ldm_x4(uint32_t* r, uint32_t addr) {
    asm volatile("ldmatrix.sync.aligned.m8n8.x4.shared.b16 {%0,%1,%2,%3}, [%4];"
                 : "=r"(r[0]), "=r"(r[1]), "=r"(r[2]), "=r"(r[3]) : "r"(addr));
}
__device__ __forceinline__ void mma_bf16(float* d, const uint32_t* a, const uint32_t* b) {
    asm volatile(
        "mma.sync.aligned.m16n8k16.row.col.f32.bf16.bf16.f32 "
        "{%0,%1,%2,%3}, {%4,%5,%6,%7}, {%8,%9}, {%0,%1,%2,%3};"
        : "+f"(d[0]), "+f"(d[1]), "+f"(d[2]), "+f"(d[3])
        : "r"(a[0]), "r"(a[1]), "r"(a[2]), "r"(a[3]), "r"(b[0]), "r"(b[1]));
}
// XOR swizzle: row stride 256B (128 bf16)
__device__ __forceinline__ uint32_t swz(int row, int kByte) {
    return (uint32_t)(row * 256 + (kByte ^ ((row & 7) << 4)));
}

// SMEM layout (bytes)
#define SM_BIAS 0
#define SM_ATT  512
#define SM_AHI  1536
#define SM_ALO  (SM_AHI + 16384)
#define SM_BHI  (SM_ALO + 16384)
#define SM_BLO  (SM_BHI + 32768)
#define SM_TOTAL (SM_BLO + 32768)   // 99840

// ---------------- init: dtype detection (side stream) ----------------
__global__ void init_kernel(const void* __restrict__ idx, int nscan, int nnodes) {
    __shared__ int bad;
    if (threadIdx.x == 0) bad = 0;
    __syncthreads();
    const long long* p = (const long long*)idx;
    int ok = 1;
    for (int i = threadIdx.x; i < nscan; i += blockDim.x) {
        long long v = p[i];
        if (v < 0 || v >= (long long)nnodes) ok = 0;
    }
    if (!ok) atomicExch(&bad, 1);
    __syncthreads();
    if (threadIdx.x == 0) g_is64 = bad ? 0 : 1;
}

// ---------------- prep: W split only ----------------
__global__ void prep_kernel(const float* __restrict__ W) {
    for (int idx2 = blockIdx.x * blockDim.x + threadIdx.x; idx2 < HC * IN_CH;
         idx2 += blockDim.x * gridDim.x) {
        int n = idx2 >> 7;
        int k = idx2 & 127;
        float w = W[idx2];
        __nv_bfloat16 hi = __float2bfloat16(w);
        float rem = w - __bfloat162float(hi);
        __nv_bfloat16 lo = __float2bfloat16(rem);
        uint32_t off = swz(n, k * 2) >> 1;
        g_Whi[off] = __bfloat16_as_ushort(hi);
        g_Wlo[off] = __bfloat16_as_ushort(lo);
    }
}

// ---------------- edge decode (overlaps with GEMM on side stream) ----------------
__global__ __launch_bounds__(256) void decode_kernel(const void* __restrict__ idx, int E) {
    int i = blockIdx.x * blockDim.x + threadIdx.x;
    if (i >= E) return;
    int is64 = g_is64;
    int s = ldidx(idx, i, is64);
    int t = ldidx(idx, (long long)E + i, is64);
    g_edges[i] = make_int2(s, t);
}

// ---------------- mma.sync GEMM + fused exp(alpha_s) epilogue ----------------
// 64x128 tile per CTA, 2 CTAs/SM; 8 warps in 2x4; warp tile 32x32.
// Mainloop: 24 flattened (product, ks) steps, double-buffered ldsm fragments.
__global__ void __launch_bounds__(256, 2)
gat_gemm_kernel(const float* __restrict__ X, const float* __restrict__ bias,
                const float* __restrict__ att, int M) {
    extern __shared__ char smem[];
    const uint32_t sb = smem_u32(smem);
    const int tid = threadIdx.x, lane = tid & 31, wid = tid >> 5;
    const int rowBase = blockIdx.x * TILE_M;

    if (tid < 128) ((float*)(smem + SM_BIAS))[tid] = bias[tid];
    ((float*)(smem + SM_ATT))[tid] = att[tid];

    // async copy of pre-swizzled W hi/lo (32 KB each)
    {
        const char* wh = (const char*)g_Whi;
        const char* wl = (const char*)g_Wlo;
#pragma unroll
        for (int it = 0; it < 8; it++) {
            int g = (tid + it * 256) * 16;
            cp_async16(sb + SM_BHI + g, wh + g);
            cp_async16(sb + SM_BLO + g, wl + g);
        }
        asm volatile("cp.async.commit_group;");
    }
    // A tile: load fp32 X, split into bf16 hi/lo, swizzled
#pragma unroll
    for (int it = 0; it < 8; it++) {
        int g = tid + it * 256;      // 0..2047
        int r = g >> 5;
        int c4 = (g & 31) * 4;
        int grow = rowBase + r;
        float4 v = make_float4(0.f, 0.f, 0.f, 0.f);
        if (grow < M) v = __ldg((const float4*)(X + (size_t)grow * IN_CH + c4));
        __nv_bfloat16 h0 = __float2bfloat16(v.x);
        __nv_bfloat16 h1 = __float2bfloat16(v.y);
        __nv_bfloat16 h2 = __float2bfloat16(v.z);
        __nv_bfloat16 h3 = __float2bfloat16(v.w);
        __nv_bfloat16 l0 = __float2bfloat16(v.x - __bfloat162float(h0));
        __nv_bfloat16 l1 = __float2bfloat16(v.y - __bfloat162float(h1));
        __nv_bfloat16 l2 = __float2bfloat16(v.z - __bfloat162float(h2));
        __nv_bfloat16 l3 = __float2bfloat16(v.w - __bfloat162float(h3));
        uint32_t hiA = ((uint32_t)__bfloat16_as_ushort(h1) << 16) | __bfloat16_as_ushort(h0);
        uint32_t hiB = ((uint32_t)__bfloat16_as_ushort(h3) << 16) | __bfloat16_as_ushort(h2);
        uint32_t loA = ((uint32_t)__bfloat16_as_ushort(l1) << 16) | __bfloat16_as_ushort(l0);
        uint32_t loB = ((uint32_t)__bfloat16_as_ushort(l3) << 16) | __bfloat16_as_ushort(l2);
        uint32_t off = swz(r, c4 * 2);
        *(uint2*)(smem + SM_AHI + off) = make_uint2(hiA, hiB);
        *(uint2*)(smem + SM_ALO + off) = make_uint2(loA, loB);
    }
    asm volatile("cp.async.wait_group 0;" ::: "memory");
    __syncthreads();

    const int wr = wid & 1, wc = wid >> 1;
    const int mrow = wr * 32;
    const int ncol = wc * 32;

    float acc[2][4][4];
#pragma unroll
    for (int mt = 0; mt < 2; mt++)
#pragma unroll
        for (int nt = 0; nt < 4; nt++)
#pragma unroll
            for (int i = 0; i < 4; i++) acc[mt][nt][i] = 0.f;

    const int a_row = (lane & 15);
    const int a_koff = (lane >> 4) * 8;
    const int b_nr = (lane & 7) + ((lane >> 4) & 1) * 8;
    const int b_koff = ((lane >> 3) & 1) * 8;

    // product p: 0 = Ahi*Bhi, 1 = Alo*Bhi, 2 = Ahi*Blo
    const uint32_t Abase0 = sb + SM_AHI, Abase1 = sb + SM_ALO;
    const uint32_t Bbase0 = sb + SM_BHI, Bbase1 = sb + SM_BLO;

    uint32_t afr[2][2][4], bfr[2][2][4];

    // fragment loader for flattened step (p = step/8, ks = step%8)
    auto load_frags = [&](int step, int buf) {
        const int p = step >> 3, ks = step & 7, k0 = ks * 16;
        const uint32_t Ab = (p == 1) ? Abase1 : Abase0;
        const uint32_t Bb = (p == 2) ? Bbase1 : Bbase0;
        ldm_x4(afr[buf][0], Ab + swz(mrow + a_row, (k0 + a_koff) * 2));
        ldm_x4(afr[buf][1], Ab + swz(mrow + 16 + a_row, (k0 + a_koff) * 2));
        ldm_x4(bfr[buf][0], Bb + swz(ncol + b_nr, (k0 + b_koff) * 2));
        ldm_x4(bfr[buf][1], Bb + swz(ncol + 16 + b_nr, (k0 + b_koff) * 2));
    };

    load_frags(0, 0);
#pragma unroll
    for (int i = 0; i < 24; i++) {
        const int cb = i & 1;
        if (i < 23) load_frags(i + 1, cb ^ 1);
#pragma unroll
        for (int mt = 0; mt < 2; mt++)
#pragma unroll
            for (int nt = 0; nt < 4; nt++)
                mma_bf16(acc[mt][nt], afr[cb][mt], &bfr[cb][nt >> 1][(nt & 1) * 2]);
    }

    // epilogue: bias, fp16 store of h, fused exp(0.01*alpha_s) (head = wc)
    const float* s_bias = (const float*)(smem + SM_BIAS);
    const float* s_att = (const float*)(smem + SM_ATT);
    const int q = lane & 3, rg = lane >> 2;

#pragma unroll
    for (int mt = 0; mt < 2; mt++) {
#pragma unroll
        for (int hh = 0; hh < 2; hh++) {
            const int r = mrow + mt * 16 + hh * 8 + rg;
            const int grow = rowBase + r;
            const bool valid = grow < M;
            float ps = 0.f;
#pragma unroll
            for (int nt = 0; nt < 4; nt++) {
                const int c0 = nt * 8 + 2 * q;
                const int col = ncol + c0;
                float v0 = acc[mt][nt][hh * 2 + 0] + s_bias[col];
                float v1 = acc[mt][nt][hh * 2 + 1] + s_bias[col + 1];
                if (valid) {
                    __half2 hv = __floats2half2_rn(v0, v1);
                    g_h16[(size_t)grow * 64 + wc * 16 + nt * 4 + q] = *(const uint32_t*)&hv;
                }
                ps += v0 * s_att[wc * 64 + 32 + c0] + v1 * s_att[wc * 64 + 33 + c0];
            }
#pragma unroll
            for (int o = 1; o <= 2; o <<= 1)
                ps += __shfl_xor_sync(0xffffffffu, ps, o);
            if (q == 0 && valid)
                g_as[(size_t)grow * HEADS + wc] = __expf(0.01f * ps);
        }
    }
}

// ---------------- E1: denominator red + early PDL trigger ----------------
__global__ __launch_bounds__(256) void edge_pass1(int E) {
    // allow the dependent agg kernel to start launching ASAP
    asm volatile("griddepcontrol.launch_dependents;");
    int i = blockIdx.x * blockDim.x + threadIdx.x;
    if (i >= E) return;
    int2 st = __ldg((const int2*)&g_edges[i]);
    float4 w = __ldg((const float4*)(g_as + (size_t)st.x * HEADS));
    red_v4(g_den + (size_t)st.y * HEADS, w);
}

// ---------------- E3: weighted aggregation, 8 lanes per edge (fp16 h) ----------
// PDL: prefetch everything independent of pass1, then wait, then den + red.
__global__ __launch_bounds__(256) void agg_kernel(int E, float* __restrict__ out) {
    int gtid = blockIdx.x * blockDim.x + threadIdx.x;
    int eid = gtid >> 3;
    if (eid >= E) {
        asm volatile("griddepcontrol.wait;" ::: "memory");
        return;
    }
    int lg = gtid & 7;
    int2 st = __ldg((const int2*)&g_edges[eid]);
    float4 a = __ldg((const float4*)(g_as + (size_t)st.x * HEADS));
    const uint2* hp = (const uint2*)(g_h16 + (size_t)st.x * 64);
    uint2 u0 = __ldg(hp + 0 * 8 + lg);
    uint2 u1 = __ldg(hp + 1 * 8 + lg);
    uint2 u2 = __ldg(hp + 2 * 8 + lg);
    uint2 u3 = __ldg(hp + 3 * 8 + lg);
    // wait for pass1 (denominators) to complete + be visible
    asm volatile("griddepcontrol.wait;" ::: "memory");
    float4 den = __ldg((const float4*)(g_den + (size_t)st.y * HEADS));
    float w0 = 0.25f * a.x / (den.x + EPS_F);
    float w1 = 0.25f * a.y / (den.y + EPS_F);
    float w2 = 0.25f * a.z / (den.z + EPS_F);
    float w3 = 0.25f * a.w / (den.w + EPS_F);
    float2 a01 = __half22float2(*(const __half2*)&u0.x);
    float2 a23 = __half22float2(*(const __half2*)&u0.y);
    float2 b01 = __half22float2(*(const __half2*)&u1.x);
    float2 b23 = __half22float2(*(const __half2*)&u1.y);
    float2 c01 = __half22float2(*(const __half2*)&u2.x);
    float2 c23 = __half22float2(*(const __half2*)&u2.y);
    float2 d01 = __half22float2(*(const __half2*)&u3.x);
    float2 d23 = __half22float2(*(const __half2*)&u3.y);
    float4 v;
    v.x = w0 * a01.x + w1 * b01.x + w2 * c01.x + w3 * d01.x;
    v.y = w0 * a01.y + w1 * b01.y + w2 * c01.y + w3 * d01.y;
    v.z = w0 * a23.x + w1 * b23.x + w2 * c23.x + w3 * d23.x;
    v.w = w0 * a23.y + w1 * b23.y + w2 * c23.y + w3 * d23.y;
    red_v4(out + (size_t)st.y * OUT_CH + lg * 4, v);
}

// ---------------- launch ----------------
extern "C" void kernel_launch(void* const* d_in, const int* in_sizes, int n_in,
                              void* d_out, int out_size) {
    const float* X    = (const float*)d_in[0];
    const void*  eidx = d_in[1];
    const float* W    = (const float*)d_in[2];
    const float* bias = (const float*)d_in[3];
    const float* att  = (const float*)d_in[4];
    float* out = (float*)d_out;

    int M = in_sizes[0] / IN_CH;          // nodes
    int E = in_sizes[1] / 2;              // edges

    static cudaStream_t s1 = nullptr;
    static cudaEvent_t evFork = nullptr, evJoin = nullptr;
    static void* denPtr = nullptr;
    if (!s1) {
        cudaStreamCreateWithFlags(&s1, cudaStreamNonBlocking);
        cudaEventCreateWithFlags(&evFork, cudaEventDisableTiming);
        cudaEventCreateWithFlags(&evJoin, cudaEventDisableTiming);
        cudaGetSymbolAddress(&denPtr, g_den);
        cudaFuncSetAttribute(gat_gemm_kernel,
                             cudaFuncAttributeMaxDynamicSharedMemorySize, SM_TOTAL);
    }

    int nscan = E < 2048 ? E : 2048;

    // fork FIRST: detection + decode + memsets start at t=0 on s1
    cudaEventRecord(evFork, 0);
    cudaStreamWaitEvent(s1, evFork, 0);
    init_kernel<<<1, 256, 0, s1>>>(eidx, nscan, M);
    decode_kernel<<<(E + 255) / 256, 256, 0, s1>>>(eidx, E);
    cudaMemsetAsync(d_out, 0, (size_t)out_size * sizeof(float), s1);
    cudaMemsetAsync(denPtr, 0, (size_t)M * HEADS * sizeof(float), s1);
    cudaEventRecord(evJoin, s1);

    prep_kernel<<<32, 256>>>(W);

    gat_gemm_kernel<<<(M + TILE_M - 1) / TILE_M, 256, SM_TOTAL>>>(X, bias, att, M);

    // join before the edge phase
    cudaStreamWaitEvent(0, evJoin, 0);

    edge_pass1<<<(E + 255) / 256, 256>>>(E);

    // agg with programmatic stream serialization (PDL pair with edge_pass1)
    {
        long long aggThreads = (long long)E * 8;
        cudaLaunchConfig_t cfg = {};
        cfg.gridDim = dim3((unsigned)((aggThreads + 255) / 256));
        cfg.blockDim = dim3(256);
        cfg.dynamicSmemBytes = 0;
        cfg.stream = 0;
        cudaLaunchAttribute attr[1];
        attr[0].id = cudaLaunchAttributeProgrammaticStreamSerialization;
        attr[0].val.programmaticStreamSerializationAllowed = 1;
        cfg.attrs = attr;
        cfg.numAttrs = 1;
        cudaLaunchKernelEx(&cfg, agg_kernel, E, out);
    }
}

// round 16
// speedup vs baseline: 1.0052x; 1.0052x over previous
#include <cuda_runtime.h>
#include <cuda_bf16.h>
#include <cuda_fp16.h>
#include <cstdint>

#define N_NODES_C 100000
#define N_EDGES_C 800000
#define HEADS 4
#define OUT_CH 32
#define IN_CH 128
#define HC 128            // HEADS*OUT_CH
#define EPS_F 1e-8f
#define TILE_M 64

// ---------------- device scratch (no allocs allowed) ----------------
__device__ __align__(16) uint32_t g_h16[(size_t)N_NODES_C * 64]; // h as half2 [N][64]
__device__ __align__(16) float g_as[N_NODES_C * HEADS];          // exp(0.01*alpha_s)
__device__ __align__(16) float g_den[N_NODES_C * HEADS];         // softmax denominators
__device__ __align__(16) int2  g_edges[N_EDGES_C];               // decoded (s,t)
__device__ int g_is64;                                           // edge index dtype flag
__device__ __align__(16) unsigned short g_Whi[HC * 128];         // W bf16 hi, swizzled
__device__ __align__(16) unsigned short g_Wlo[HC * 128];         // W bf16 lo, swizzled

__device__ __forceinline__ int ldidx(const void* p, long long i, int is64) {
    return is64 ? (int)((const long long*)p)[i] : ((const int*)p)[i];
}
__device__ __forceinline__ void red_v4(float* ptr, float4 v) {
    asm volatile("red.global.add.v4.f32 [%0], {%1,%2,%3,%4};"
                 :: "l"(ptr), "f"(v.x), "f"(v.y), "f"(v.z), "f"(v.w) : "memory");
}
__device__ __forceinline__ uint32_t smem_u32(const void* p) {
    uint32_t a;
    asm("{ .reg .u64 t; cvta.to.shared.u64 t, %1; cvt.u32.u64 %0, t; }" : "=r"(a) : "l"(p));
    return a;
}
__device__ __forceinline__ void cp_async16(uint32_t saddr, const void* gaddr) {
    asm volatile("cp.async.cg.shared.global [%0], [%1], 16;" :: "r"(saddr), "l"(gaddr));
}
__device__ __forceinline__ void ldm_x4(uint32_t* r, uint32_t addr) {
    asm volatile("ldmatrix.sync.aligned.m8n8.x4.shared.b16 {%0,%1,%2,%3}, [%4];"
                 : "=r"(r[0]), "=r"(r[1]), "=r"(r[2]), "=r"(r[3]) : "r"(addr));
}
__device__ __forceinline__ void mma_bf16(float* d, const uint32_t* a, const uint32_t* b) {
    asm volatile(
        "mma.sync.aligned.m16n8k16.row.col.f32.bf16.bf16.f32 "
        "{%0,%1,%2,%3}, {%4,%5,%6,%7}, {%8,%9}, {%0,%1,%2,%3};"
        : "+f"(d[0]), "+f"(d[1]), "+f"(d[2]), "+f"(d[3])
        : "r"(a[0]), "r"(a[1]), "r"(a[2]), "r"(a[3]), "r"(b[0]), "r"(b[1]));
}
// XOR swizzle: row stride 256B (128 bf16)
__device__ __forceinline__ uint32_t swz(int row, int kByte) {
    return (uint32_t)(row * 256 + (kByte ^ ((row & 7) << 4)));
}

// SMEM layout (bytes): A hi/lo (16 KB each) + ONE staged B buffer (32 KB)
#define SM_BIAS 0
#define SM_ATT  512
#define SM_AHI  1536
#define SM_ALO  (SM_AHI + 16384)
#define SM_B    (SM_ALO + 16384)
#define SM_TOTAL (SM_B + 32768)     // 67072 -> 3 CTAs/SM

// ---------------- init: dtype detection (side stream) ----------------
__global__ void init_kernel(const void* __restrict__ idx, int nscan, int nnodes) {
    __shared__ int bad;
    if (threadIdx.x == 0) bad = 0;
    __syncthreads();
    const long long* p = (const long long*)idx;
    int ok = 1;
    for (int i = threadIdx.x; i < nscan; i += blockDim.x) {
        long long v = p[i];
        if (v < 0 || v >= (long long)nnodes) ok = 0;
    }
    if (!ok) atomicExch(&bad, 1);
    __syncthreads();
    if (threadIdx.x == 0) g_is64 = bad ? 0 : 1;
}

// ---------------- prep: W split only ----------------
__global__ void prep_kernel(const float* __restrict__ W) {
    for (int idx2 = blockIdx.x * blockDim.x + threadIdx.x; idx2 < HC * IN_CH;
         idx2 += blockDim.x * gridDim.x) {
        int n = idx2 >> 7;
        int k = idx2 & 127;
        float w = W[idx2];
        __nv_bfloat16 hi = __float2bfloat16(w);
        float rem = w - __bfloat162float(hi);
        __nv_bfloat16 lo = __float2bfloat16(rem);
        uint32_t off = swz(n, k * 2) >> 1;
        g_Whi[off] = __bfloat16_as_ushort(hi);
        g_Wlo[off] = __bfloat16_as_ushort(lo);
    }
}

// ---------------- edge decode (overlaps with GEMM on side stream) ----------------
__global__ __launch_bounds__(256) void decode_kernel(const void* __restrict__ idx, int E) {
    int i = blockIdx.x * blockDim.x + threadIdx.x;
    if (i >= E) return;
    int is64 = g_is64;
    int s = ldidx(idx, i, is64);
    int t = ldidx(idx, (long long)E + i, is64);
    g_edges[i] = make_int2(s, t);
}

// ---------------- mma.sync GEMM + fused exp(alpha_s) epilogue ----------------
// 64x128 tile per CTA, 3 CTAs/SM; 8 warps in 2x4; warp tile 32x32.
// B staged through one 32KB buffer: phase A = {Ahi,Alo}xBhi, reload, phase B = AhixBlo.
__global__ void __launch_bounds__(256, 3)
gat_gemm_kernel(const float* __restrict__ X, const float* __restrict__ bias,
                const float* __restrict__ att, int M) {
    extern __shared__ char smem[];
    const uint32_t sb = smem_u32(smem);
    const int tid = threadIdx.x, lane = tid & 31, wid = tid >> 5;
    const int rowBase = blockIdx.x * TILE_M;

    if (tid < 128) ((float*)(smem + SM_BIAS))[tid] = bias[tid];
    ((float*)(smem + SM_ATT))[tid] = att[tid];

    // async copy of pre-swizzled W-hi (32 KB) into the staged B buffer
    {
        const char* wh = (const char*)g_Whi;
#pragma unroll
        for (int it = 0; it < 8; it++) {
            int g = (tid + it * 256) * 16;
            cp_async16(sb + SM_B + g, wh + g);
        }
        asm volatile("cp.async.commit_group;");
    }
    // A tile: load fp32 X, split into bf16 hi/lo, swizzled
#pragma unroll
    for (int it = 0; it < 8; it++) {
        int g = tid + it * 256;      // 0..2047
        int r = g >> 5;
        int c4 = (g & 31) * 4;
        int grow = rowBase + r;
        float4 v = make_float4(0.f, 0.f, 0.f, 0.f);
        if (grow < M) v = __ldg((const float4*)(X + (size_t)grow * IN_CH + c4));
        __nv_bfloat16 h0 = __float2bfloat16(v.x);
        __nv_bfloat16 h1 = __float2bfloat16(v.y);
        __nv_bfloat16 h2 = __float2bfloat16(v.z);
        __nv_bfloat16 h3 = __float2bfloat16(v.w);
        __nv_bfloat16 l0 = __float2bfloat16(v.x - __bfloat162float(h0));
        __nv_bfloat16 l1 = __float2bfloat16(v.y - __bfloat162float(h1));
        __nv_bfloat16 l2 = __float2bfloat16(v.z - __bfloat162float(h2));
        __nv_bfloat16 l3 = __float2bfloat16(v.w - __bfloat162float(h3));
        uint32_t hiA = ((uint32_t)__bfloat16_as_ushort(h1) << 16) | __bfloat16_as_ushort(h0);
        uint32_t hiB = ((uint32_t)__bfloat16_as_ushort(h3) << 16) | __bfloat16_as_ushort(h2);
        uint32_t loA = ((uint32_t)__bfloat16_as_ushort(l1) << 16) | __bfloat16_as_ushort(l0);
        uint32_t loB = ((uint32_t)__bfloat16_as_ushort(l3) << 16) | __bfloat16_as_ushort(l2);
        uint32_t off = swz(r, c4 * 2);
        *(uint2*)(smem + SM_AHI + off) = make_uint2(hiA, hiB);
        *(uint2*)(smem + SM_ALO + off) = make_uint2(loA, loB);
    }
    asm volatile("cp.async.wait_group 0;" ::: "memory");
    __syncthreads();

    const int wr = wid & 1, wc = wid >> 1;
    const int mrow = wr * 32;
    const int ncol = wc * 32;

    float acc[2][4][4];
#pragma unroll
    for (int mt = 0; mt < 2; mt++)
#pragma unroll
        for (int nt = 0; nt < 4; nt++)
#pragma unroll
            for (int i = 0; i < 4; i++) acc[mt][nt][i] = 0.f;

    const int a_row = (lane & 15);
    const int a_koff = (lane >> 4) * 8;
    const int b_nr = (lane & 7) + ((lane >> 4) & 1) * 8;
    const int b_koff = ((lane >> 3) & 1) * 8;

    // Phase A: Ahi*Bhi (p=0) and Alo*Bhi (p=1), B buffer holds W-hi
#pragma unroll
    for (int p = 0; p < 2; p++) {
        const uint32_t Ab = sb + (p == 1 ? SM_ALO : SM_AHI);
        const uint32_t Bb = sb + SM_B;
#pragma unroll
        for (int ks = 0; ks < 8; ks++) {
            const int k0 = ks * 16;
            uint32_t a[2][4];
#pragma unroll
            for (int mt = 0; mt < 2; mt++) {
                int row = mrow + mt * 16 + a_row;
                ldm_x4(a[mt], Ab + swz(row, (k0 + a_koff) * 2));
            }
            uint32_t b[2][4];
#pragma unroll
            for (int np = 0; np < 2; np++) {
                int row = ncol + np * 16 + b_nr;
                ldm_x4(b[np], Bb + swz(row, (k0 + b_koff) * 2));
            }
#pragma unroll
            for (int mt = 0; mt < 2; mt++)
#pragma unroll
                for (int nt = 0; nt < 4; nt++)
                    mma_bf16(acc[mt][nt], a[mt], &b[nt >> 1][(nt & 1) * 2]);
        }
    }

    // Reload staged B buffer with W-lo (L2-hot), then Phase B
    __syncthreads();
    {
        const char* wl = (const char*)g_Wlo;
#pragma unroll
        for (int it = 0; it < 8; it++) {
            int g = (tid + it * 256) * 16;
            cp_async16(sb + SM_B + g, wl + g);
        }
        asm volatile("cp.async.commit_group;");
        asm volatile("cp.async.wait_group 0;" ::: "memory");
    }
    __syncthreads();

    // Phase B: Ahi*Blo
    {
        const uint32_t Ab = sb + SM_AHI;
        const uint32_t Bb = sb + SM_B;
#pragma unroll
        for (int ks = 0; ks < 8; ks++) {
            const int k0 = ks * 16;
            uint32_t a[2][4];
#pragma unroll
            for (int mt = 0; mt < 2; mt++) {
                int row = mrow + mt * 16 + a_row;
                ldm_x4(a[mt], Ab + swz(row, (k0 + a_koff) * 2));
            }
            uint32_t b[2][4];
#pragma unroll
            for (int np = 0; np < 2; np++) {
                int row = ncol + np * 16 + b_nr;
                ldm_x4(b[np], Bb + swz(row, (k0 + b_koff) * 2));
            }
#pragma unroll
            for (int mt = 0; mt < 2; mt++)
#pragma unroll
                for (int nt = 0; nt < 4; nt++)
                    mma_bf16(acc[mt][nt], a[mt], &b[nt >> 1][(nt & 1) * 2]);
        }
    }

    // epilogue: bias, fp16 store of h, fused exp(0.01*alpha_s) (head = wc)
    const float* s_bias = (const float*)(smem + SM_BIAS);
    const float* s_att = (const float*)(smem + SM_ATT);
    const int q = lane & 3, rg = lane >> 2;

#pragma unroll
    for (int mt = 0; mt < 2; mt++) {
#pragma unroll
        for (int hh = 0; hh < 2; hh++) {
            const int r = mrow + mt * 16 + hh * 8 + rg;
            const int grow = rowBase + r;
            const bool valid = grow < M;
            float ps = 0.f;
#pragma unroll
            for (int nt = 0; nt < 4; nt++) {
                const int c0 = nt * 8 + 2 * q;
                const int col = ncol + c0;
                float v0 = acc[mt][nt][hh * 2 + 0] + s_bias[col];
                float v1 = acc[mt][nt][hh * 2 + 1] + s_bias[col + 1];
                if (valid) {
                    __half2 hv = __floats2half2_rn(v0, v1);
                    g_h16[(size_t)grow * 64 + wc * 16 + nt * 4 + q] = *(const uint32_t*)&hv;
                }
                ps += v0 * s_att[wc * 64 + 32 + c0] + v1 * s_att[wc * 64 + 33 + c0];
            }
#pragma unroll
            for (int o = 1; o <= 2; o <<= 1)
                ps += __shfl_xor_sync(0xffffffffu, ps, o);
            if (q == 0 && valid)
                g_as[(size_t)grow * HEADS + wc] = __expf(0.01f * ps);
        }
    }
}

// ---------------- E1: denominator red + early PDL trigger ----------------
__global__ __launch_bounds__(256) void edge_pass1(int E) {
    // allow the dependent agg kernel to start launching ASAP
    asm volatile("griddepcontrol.launch_dependents;");
    int i = blockIdx.x * blockDim.x + threadIdx.x;
    if (i >= E) return;
    int2 st = __ldg((const int2*)&g_edges[i]);
    float4 w = __ldg((const float4*)(g_as + (size_t)st.x * HEADS));
    red_v4(g_den + (size_t)st.y * HEADS, w);
}

// ---------------- E3: weighted aggregation, 8 lanes per edge (fp16 h) ----------
// PDL: prefetch everything independent of pass1, then wait, then den + red.
__global__ __launch_bounds__(256) void agg_kernel(int E, float* __restrict__ out) {
    int gtid = blockIdx.x * blockDim.x + threadIdx.x;
    int eid = gtid >> 3;
    if (eid >= E) {
        asm volatile("griddepcontrol.wait;" ::: "memory");
        return;
    }
    int lg = gtid & 7;
    int2 st = __ldg((const int2*)&g_edges[eid]);
    float4 a = __ldg((const float4*)(g_as + (size_t)st.x * HEADS));
    const uint2* hp = (const uint2*)(g_h16 + (size_t)st.x * 64);
    uint2 u0 = __ldg(hp + 0 * 8 + lg);
    uint2 u1 = __ldg(hp + 1 * 8 + lg);
    uint2 u2 = __ldg(hp + 2 * 8 + lg);
    uint2 u3 = __ldg(hp + 3 * 8 + lg);
    // wait for pass1 (denominators) to complete + be visible
    asm volatile("griddepcontrol.wait;" ::: "memory");
    float4 den = __ldg((const float4*)(g_den + (size_t)st.y * HEADS));
    float w0 = 0.25f * a.x / (den.x + EPS_F);
    float w1 = 0.25f * a.y / (den.y + EPS_F);
    float w2 = 0.25f * a.z / (den.z + EPS_F);
    float w3 = 0.25f * a.w / (den.w + EPS_F);
    float2 a01 = __half22float2(*(const __half2*)&u0.x);
    float2 a23 = __half22float2(*(const __half2*)&u0.y);
    float2 b01 = __half22float2(*(const __half2*)&u1.x);
    float2 b23 = __half22float2(*(const __half2*)&u1.y);
    float2 c01 = __half22float2(*(const __half2*)&u2.x);
    float2 c23 = __half22float2(*(const __half2*)&u2.y);
    float2 d01 = __half22float2(*(const __half2*)&u3.x);
    float2 d23 = __half22float2(*(const __half2*)&u3.y);
    float4 v;
    v.x = w0 * a01.x + w1 * b01.x + w2 * c01.x + w3 * d01.x;
    v.y = w0 * a01.y + w1 * b01.y + w2 * c01.y + w3 * d01.y;
    v.z = w0 * a23.x + w1 * b23.x + w2 * c23.x + w3 * d23.x;
    v.w = w0 * a23.y + w1 * b23.y + w2 * c23.y + w3 * d23.y;
    red_v4(out + (size_t)st.y * OUT_CH + lg * 4, v);
}

// ---------------- launch ----------------
extern "C" void kernel_launch(void* const* d_in, const int* in_sizes, int n_in,
                              void* d_out, int out_size) {
    const float* X    = (const float*)d_in[0];
    const void*  eidx = d_in[1];
    const float* W    = (const float*)d_in[2];
    const float* bias = (const float*)d_in[3];
    const float* att  = (const float*)d_in[4];
    float* out = (float*)d_out;

    int M = in_sizes[0] / IN_CH;          // nodes
    int E = in_sizes[1] / 2;              // edges

    static cudaStream_t s1 = nullptr;
    static cudaEvent_t evFork = nullptr, evJoin = nullptr;
    static void* denPtr = nullptr;
    if (!s1) {
        cudaStreamCreateWithFlags(&s1, cudaStreamNonBlocking);
        cudaEventCreateWithFlags(&evFork, cudaEventDisableTiming);
        cudaEventCreateWithFlags(&evJoin, cudaEventDisableTiming);
        cudaGetSymbolAddress(&denPtr, g_den);
        cudaFuncSetAttribute(gat_gemm_kernel,
                             cudaFuncAttributeMaxDynamicSharedMemorySize, SM_TOTAL);
    }

    int nscan = E < 2048 ? E : 2048;

    // fork FIRST: detection + decode + memsets start at t=0 on s1
    cudaEventRecord(evFork, 0);
    cudaStreamWaitEvent(s1, evFork, 0);
    init_kernel<<<1, 256, 0, s1>>>(eidx, nscan, M);
    decode_kernel<<<(E + 255) / 256, 256, 0, s1>>>(eidx, E);
    cudaMemsetAsync(d_out, 0, (size_t)out_size * sizeof(float), s1);
    cudaMemsetAsync(denPtr, 0, (size_t)M * HEADS * sizeof(float), s1);
    cudaEventRecord(evJoin, s1);

    prep_kernel<<<32, 256>>>(W);

    gat_gemm_kernel<<<(M + TILE_M - 1) / TILE_M, 256, SM_TOTAL>>>(X, bias, att, M);

    // join before the edge phase
    cudaStreamWaitEvent(0, evJoin, 0);

    edge_pass1<<<(E + 255) / 256, 256>>>(E);

    // agg with programmatic stream serialization (PDL pair with edge_pass1)
    {
        long long aggThreads = (long long)E * 8;
        cudaLaunchConfig_t cfg = {};
        cfg.gridDim = dim3((unsigned)((aggThreads + 255) / 256));
        cfg.blockDim = dim3(256);
        cfg.dynamicSmemBytes = 0;
        cfg.stream = 0;
        cudaLaunchAttribute attr[1];
        attr[0].id = cudaLaunchAttributeProgrammaticStreamSerialization;
        attr[0].val.programmaticStreamSerializationAllowed = 1;
        cfg.attrs = attr;
        cfg.numAttrs = 1;
        cudaLaunchKernelEx(&cfg, agg_kernel, E, out);
    }
}

// round 17
// speedup vs baseline: 1.1779x; 1.1719x over previous
#include <cuda_runtime.h>
#include <cuda_bf16.h>
#include <cuda_fp16.h>
#include <cstdint>

#define N_NODES_C 100000
#define N_EDGES_C 800000
#define HEADS 4
#define OUT_CH 32
#define IN_CH 128
#define HC 128            // HEADS*OUT_CH
#define EPS_F 1e-8f
#define TILE_M 64

// ---------------- device scratch (no allocs allowed) ----------------
__device__ __align__(16) uint32_t g_h16[(size_t)N_NODES_C * 64]; // h as half2 [N][64]
__device__ __align__(16) float g_as[N_NODES_C * HEADS];          // exp(0.01*alpha_s)
__device__ __align__(16) float g_den[N_NODES_C * HEADS];         // softmax denominators
__device__ __align__(16) int2  g_edges[N_EDGES_C];               // decoded (s,t)
__device__ int g_is64;                                           // edge index dtype flag
__device__ __align__(16) unsigned short g_Whi[HC * 128];         // W bf16 hi, swizzled
__device__ __align__(16) unsigned short g_Wlo[HC * 128];         // W bf16 lo, swizzled

__device__ __forceinline__ int ldidx(const void* p, long long i, int is64) {
    return is64 ? (int)((const long long*)p)[i] : ((const int*)p)[i];
}
__device__ __forceinline__ void red_v4(float* ptr, float4 v) {
    asm volatile("red.global.add.v4.f32 [%0], {%1,%2,%3,%4};"
                 :: "l"(ptr), "f"(v.x), "f"(v.y), "f"(v.z), "f"(v.w) : "memory");
}
__device__ __forceinline__ uint32_t smem_u32(const void* p) {
    uint32_t a;
    asm("{ .reg .u64 t; cvta.to.shared.u64 t, %1; cvt.u32.u64 %0, t; }" : "=r"(a) : "l"(p));
    return a;
}
__device__ __forceinline__ void cp_async16(uint32_t saddr, const void* gaddr) {
    asm volatile("cp.async.cg.shared.global [%0], [%1], 16;" :: "r"(saddr), "l"(gaddr));
}
__device__ __forceinline__ void ldm_x4(uint32_t* r, uint32_t addr) {
    asm volatile("ldmatrix.sync.aligned.m8n8.x4.shared.b16 {%0,%1,%2,%3}, [%4];"
                 : "=r"(r[0]), "=r"(r[1]), "=r"(r[2]), "=r"(r[3]) : "r"(addr));
}
__device__ __forceinline__ void mma_bf16(float* d, const uint32_t* a, const uint32_t* b) {
    asm volatile(
        "mma.sync.aligned.m16n8k16.row.col.f32.bf16.bf16.f32 "
        "{%0,%1,%2,%3}, {%4,%5,%6,%7}, {%8,%9}, {%0,%1,%2,%3};"
        : "+f"(d[0]), "+f"(d[1]), "+f"(d[2]), "+f"(d[3])
        : "r"(a[0]), "r"(a[1]), "r"(a[2]), "r"(a[3]), "r"(b[0]), "r"(b[1]));
}
// XOR swizzle: row stride 256B (128 bf16)
__device__ __forceinline__ uint32_t swz(int row, int kByte) {
    return (uint32_t)(row * 256 + (kByte ^ ((row & 7) << 4)));
}

// SMEM layout (bytes): X staged raw in the B-lo slot, W-lo reloaded there later.
#define SM_BIAS 0
#define SM_ATT  512
#define SM_AHI  1536
#define SM_ALO  (SM_AHI + 16384)
#define SM_BHI  (SM_ALO + 16384)
#define SM_BLO  (SM_BHI + 32768)    // doubles as the 32 KB X staging buffer
#define SM_TOTAL (SM_BLO + 32768)   // 99840 -> 2 CTAs/SM

// ---------------- init: dtype detection (side stream) ----------------
__global__ void init_kernel(const void* __restrict__ idx, int nscan, int nnodes) {
    __shared__ int bad;
    if (threadIdx.x == 0) bad = 0;
    __syncthreads();
    const long long* p = (const long long*)idx;
    int ok = 1;
    for (int i = threadIdx.x; i < nscan; i += blockDim.x) {
        long long v = p[i];
        if (v < 0 || v >= (long long)nnodes) ok = 0;
    }
    if (!ok) atomicExch(&bad, 1);
    __syncthreads();
    if (threadIdx.x == 0) g_is64 = bad ? 0 : 1;
}

// ---------------- prep: W split only ----------------
__global__ void prep_kernel(const float* __restrict__ W) {
    for (int idx2 = blockIdx.x * blockDim.x + threadIdx.x; idx2 < HC * IN_CH;
         idx2 += blockDim.x * gridDim.x) {
        int n = idx2 >> 7;
        int k = idx2 & 127;
        float w = W[idx2];
        __nv_bfloat16 hi = __float2bfloat16(w);
        float rem = w - __bfloat162float(hi);
        __nv_bfloat16 lo = __float2bfloat16(rem);
        uint32_t off = swz(n, k * 2) >> 1;
        g_Whi[off] = __bfloat16_as_ushort(hi);
        g_Wlo[off] = __bfloat16_as_ushort(lo);
    }
}

// ---------------- edge decode (overlaps with GEMM on side stream) ----------------
__global__ __launch_bounds__(256) void decode_kernel(const void* __restrict__ idx, int E) {
    int i = blockIdx.x * blockDim.x + threadIdx.x;
    if (i >= E) return;
    int is64 = g_is64;
    int s = ldidx(idx, i, is64);
    int t = ldidx(idx, (long long)E + i, is64);
    g_edges[i] = make_int2(s, t);
}

// ---------------- mma.sync GEMM + fused exp(alpha_s) epilogue ----------------
// 64x128 tile per CTA, 2 CTAs/SM; 8 warps in 2x4; warp tile 32x32.
// X streamed via cp.async into a stage; W-lo reload hidden under hi-product MMAs.
__global__ void __launch_bounds__(256, 2)
gat_gemm_kernel(const float* __restrict__ X, const float* __restrict__ bias,
                const float* __restrict__ att, int M) {
    extern __shared__ char smem[];
    const uint32_t sb = smem_u32(smem);
    const int tid = threadIdx.x, lane = tid & 31, wid = tid >> 5;
    const int rowBase = blockIdx.x * TILE_M;

    if (tid < 128) ((float*)(smem + SM_BIAS))[tid] = bias[tid];
    ((float*)(smem + SM_ATT))[tid] = att[tid];

    // Stage 1: async copy W-hi -> BHI and raw X rows -> BLO(stage)
    {
        const char* wh = (const char*)g_Whi;
#pragma unroll
        for (int it = 0; it < 8; it++) {
            int g = (tid + it * 256) * 16;
            cp_async16(sb + SM_BHI + g, wh + g);
        }
#pragma unroll
        for (int it = 0; it < 8; it++) {
            int g = tid + it * 256;      // float4 index 0..2047
            int r = g >> 5;
            int c4 = (g & 31) * 4;
            int grow = rowBase + r;
            if (grow < M)
                cp_async16(sb + SM_BLO + g * 16, X + (size_t)grow * IN_CH + c4);
        }
        asm volatile("cp.async.commit_group;");
        asm volatile("cp.async.wait_group 0;" ::: "memory");
    }
    __syncthreads();

    // Stage 2: convert staged fp32 X -> bf16 hi/lo swizzled A tiles
#pragma unroll
    for (int it = 0; it < 8; it++) {
        int g = tid + it * 256;
        int r = g >> 5;
        int c4 = (g & 31) * 4;
        int grow = rowBase + r;
        float4 v = make_float4(0.f, 0.f, 0.f, 0.f);
        if (grow < M) v = *(const float4*)(smem + SM_BLO + g * 16);
        __nv_bfloat16 h0 = __float2bfloat16(v.x);
        __nv_bfloat16 h1 = __float2bfloat16(v.y);
        __nv_bfloat16 h2 = __float2bfloat16(v.z);
        __nv_bfloat16 h3 = __float2bfloat16(v.w);
        __nv_bfloat16 l0 = __float2bfloat16(v.x - __bfloat162float(h0));
        __nv_bfloat16 l1 = __float2bfloat16(v.y - __bfloat162float(h1));
        __nv_bfloat16 l2 = __float2bfloat16(v.z - __bfloat162float(h2));
        __nv_bfloat16 l3 = __float2bfloat16(v.w - __bfloat162float(h3));
        uint32_t hiA = ((uint32_t)__bfloat16_as_ushort(h1) << 16) | __bfloat16_as_ushort(h0);
        uint32_t hiB = ((uint32_t)__bfloat16_as_ushort(h3) << 16) | __bfloat16_as_ushort(h2);
        uint32_t loA = ((uint32_t)__bfloat16_as_ushort(l1) << 16) | __bfloat16_as_ushort(l0);
        uint32_t loB = ((uint32_t)__bfloat16_as_ushort(l3) << 16) | __bfloat16_as_ushort(l2);
        uint32_t off = swz(r, c4 * 2);
        *(uint2*)(smem + SM_AHI + off) = make_uint2(hiA, hiB);
        *(uint2*)(smem + SM_ALO + off) = make_uint2(loA, loB);
    }
    __syncthreads();   // stage fully consumed; A tiles visible

    // Stage 3: kick W-lo -> BLO (L2-hot); wait deferred past the hi-products
    {
        const char* wl = (const char*)g_Wlo;
#pragma unroll
        for (int it = 0; it < 8; it++) {
            int g = (tid + it * 256) * 16;
            cp_async16(sb + SM_BLO + g, wl + g);
        }
        asm volatile("cp.async.commit_group;");
    }

    const int wr = wid & 1, wc = wid >> 1;
    const int mrow = wr * 32;
    const int ncol = wc * 32;

    float acc[2][4][4];
#pragma unroll
    for (int mt = 0; mt < 2; mt++)
#pragma unroll
        for (int nt = 0; nt < 4; nt++)
#pragma unroll
            for (int i = 0; i < 4; i++) acc[mt][nt][i] = 0.f;

    const int a_row = (lane & 15);
    const int a_koff = (lane >> 4) * 8;
    const int b_nr = (lane & 7) + ((lane >> 4) & 1) * 8;
    const int b_koff = ((lane >> 3) & 1) * 8;

    // Phase A: Ahi*Bhi (p=0) and Alo*Bhi (p=1)
#pragma unroll
    for (int p = 0; p < 2; p++) {
        const uint32_t Ab = sb + (p == 1 ? SM_ALO : SM_AHI);
        const uint32_t Bb = sb + SM_BHI;
#pragma unroll
        for (int ks = 0; ks < 8; ks++) {
            const int k0 = ks * 16;
            uint32_t a[2][4];
#pragma unroll
            for (int mt = 0; mt < 2; mt++) {
                int row = mrow + mt * 16 + a_row;
                ldm_x4(a[mt], Ab + swz(row, (k0 + a_koff) * 2));
            }
            uint32_t b[2][4];
#pragma unroll
            for (int np = 0; np < 2; np++) {
                int row = ncol + np * 16 + b_nr;
                ldm_x4(b[np], Bb + swz(row, (k0 + b_koff) * 2));
            }
#pragma unroll
            for (int mt = 0; mt < 2; mt++)
#pragma unroll
                for (int nt = 0; nt < 4; nt++)
                    mma_bf16(acc[mt][nt], a[mt], &b[nt >> 1][(nt & 1) * 2]);
        }
    }

    // W-lo must be resident before Phase B
    asm volatile("cp.async.wait_group 0;" ::: "memory");
    __syncthreads();

    // Phase B: Ahi*Blo
    {
        const uint32_t Ab = sb + SM_AHI;
        const uint32_t Bb = sb + SM_BLO;
#pragma unroll
        for (int ks = 0; ks < 8; ks++) {
            const int k0 = ks * 16;
            uint32_t a[2][4];
#pragma unroll
            for (int mt = 0; mt < 2; mt++) {
                int row = mrow + mt * 16 + a_row;
                ldm_x4(a[mt], Ab + swz(row, (k0 + a_koff) * 2));
            }
            uint32_t b[2][4];
#pragma unroll
            for (int np = 0; np < 2; np++) {
                int row = ncol + np * 16 + b_nr;
                ldm_x4(b[np], Bb + swz(row, (k0 + b_koff) * 2));
            }
#pragma unroll
            for (int mt = 0; mt < 2; mt++)
#pragma unroll
                for (int nt = 0; nt < 4; nt++)
                    mma_bf16(acc[mt][nt], a[mt], &b[nt >> 1][(nt & 1) * 2]);
        }
    }

    // epilogue: bias, fp16 store of h, fused exp(0.01*alpha_s) (head = wc)
    const float* s_bias = (const float*)(smem + SM_BIAS);
    const float* s_att = (const float*)(smem + SM_ATT);
    const int q = lane & 3, rg = lane >> 2;

#pragma unroll
    for (int mt = 0; mt < 2; mt++) {
#pragma unroll
        for (int hh = 0; hh < 2; hh++) {
            const int r = mrow + mt * 16 + hh * 8 + rg;
            const int grow = rowBase + r;
            const bool valid = grow < M;
            float ps = 0.f;
#pragma unroll
            for (int nt = 0; nt < 4; nt++) {
                const int c0 = nt * 8 + 2 * q;
                const int col = ncol + c0;
                float v0 = acc[mt][nt][hh * 2 + 0] + s_bias[col];
                float v1 = acc[mt][nt][hh * 2 + 1] + s_bias[col + 1];
                if (valid) {
                    __half2 hv = __floats2half2_rn(v0, v1);
                    g_h16[(size_t)grow * 64 + wc * 16 + nt * 4 + q] = *(const uint32_t*)&hv;
                }
                ps += v0 * s_att[wc * 64 + 32 + c0] + v1 * s_att[wc * 64 + 33 + c0];
            }
#pragma unroll
            for (int o = 1; o <= 2; o <<= 1)
                ps += __shfl_xor_sync(0xffffffffu, ps, o);
            if (q == 0 && valid)
                g_as[(size_t)grow * HEADS + wc] = __expf(0.01f * ps);
        }
    }
}

// ---------------- E1: denominator red + early PDL trigger ----------------
__global__ __launch_bounds__(256) void edge_pass1(int E) {
    // allow the dependent agg kernel to start launching ASAP
    asm volatile("griddepcontrol.launch_dependents;");
    int i = blockIdx.x * blockDim.x + threadIdx.x;
    if (i >= E) return;
    int2 st = __ldg((const int2*)&g_edges[i]);
    float4 w = __ldg((const float4*)(g_as + (size_t)st.x * HEADS));
    red_v4(g_den + (size_t)st.y * HEADS, w);
}

// ---------------- E3: weighted aggregation, 8 lanes per edge (fp16 h) ----------
// PDL: prefetch everything independent of pass1, then wait, then den + red.
__global__ __launch_bounds__(256) void agg_kernel(int E, float* __restrict__ out) {
    int gtid = blockIdx.x * blockDim.x + threadIdx.x;
    int eid = gtid >> 3;
    if (eid >= E) {
        asm volatile("griddepcontrol.wait;" ::: "memory");
        return;
    }
    int lg = gtid & 7;
    int2 st = __ldg((const int2*)&g_edges[eid]);
    float4 a = __ldg((const float4*)(g_as + (size_t)st.x * HEADS));
    const uint2* hp = (const uint2*)(g_h16 + (size_t)st.x * 64);
    uint2 u0 = __ldg(hp + 0 * 8 + lg);
    uint2 u1 = __ldg(hp + 1 * 8 + lg);
    uint2 u2 = __ldg(hp + 2 * 8 + lg);
    uint2 u3 = __ldg(hp + 3 * 8 + lg);
    // wait for pass1 (denominators) to complete + be visible
    asm volatile("griddepcontrol.wait;" ::: "memory");
    float4 den = __ldg((const float4*)(g_den + (size_t)st.y * HEADS));
    float w0 = 0.25f * a.x / (den.x + EPS_F);
    float w1 = 0.25f * a.y / (den.y + EPS_F);
    float w2 = 0.25f * a.z / (den.z + EPS_F);
    float w3 = 0.25f * a.w / (den.w + EPS_F);
    float2 a01 = __half22float2(*(const __half2*)&u0.x);
    float2 a23 = __half22float2(*(const __half2*)&u0.y);
    float2 b01 = __half22float2(*(const __half2*)&u1.x);
    float2 b23 = __half22float2(*(const __half2*)&u1.y);
    float2 c01 = __half22float2(*(const __half2*)&u2.x);
    float2 c23 = __half22float2(*(const __half2*)&u2.y);
    float2 d01 = __half22float2(*(const __half2*)&u3.x);
    float2 d23 = __half22float2(*(const __half2*)&u3.y);
    float4 v;
    v.x = w0 * a01.x + w1 * b01.x + w2 * c01.x + w3 * d01.x;
    v.y = w0 * a01.y + w1 * b01.y + w2 * c01.y + w3 * d01.y;
    v.z = w0 * a23.x + w1 * b23.x + w2 * c23.x + w3 * d23.x;
    v.w = w0 * a23.y + w1 * b23.y + w2 * c23.y + w3 * d23.y;
    red_v4(out + (size_t)st.y * OUT_CH + lg * 4, v);
}

// ---------------- launch ----------------
extern "C" void kernel_launch(void* const* d_in, const int* in_sizes, int n_in,
                              void* d_out, int out_size) {
    const float* X    = (const float*)d_in[0];
    const void*  eidx = d_in[1];
    const float* W    = (const float*)d_in[2];
    const float* bias = (const float*)d_in[3];
    const float* att  = (const float*)d_in[4];
    float* out = (float*)d_out;

    int M = in_sizes[0] / IN_CH;          // nodes
    int E = in_sizes[1] / 2;              // edges

    static cudaStream_t s1 = nullptr;
    static cudaEvent_t evFork = nullptr, evJoin = nullptr;
    static void* denPtr = nullptr;
    if (!s1) {
        cudaStreamCreateWithFlags(&s1, cudaStreamNonBlocking);
        cudaEventCreateWithFlags(&evFork, cudaEventDisableTiming);
        cudaEventCreateWithFlags(&evJoin, cudaEventDisableTiming);
        cudaGetSymbolAddress(&denPtr, g_den);
        cudaFuncSetAttribute(gat_gemm_kernel,
                             cudaFuncAttributeMaxDynamicSharedMemorySize, SM_TOTAL);
    }

    int nscan = E < 2048 ? E : 2048;

    // fork FIRST: detection + decode + memsets start at t=0 on s1
    cudaEventRecord(evFork, 0);
    cudaStreamWaitEvent(s1, evFork, 0);
    init_kernel<<<1, 256, 0, s1>>>(eidx, nscan, M);
    decode_kernel<<<(E + 255) / 256, 256, 0, s1>>>(eidx, E);
    cudaMemsetAsync(d_out, 0, (size_t)out_size * sizeof(float), s1);
    cudaMemsetAsync(denPtr, 0, (size_t)M * HEADS * sizeof(float), s1);
    cudaEventRecord(evJoin, s1);

    prep_kernel<<<32, 256>>>(W);

    gat_gemm_kernel<<<(M + TILE_M - 1) / TILE_M, 256, SM_TOTAL>>>(X, bias, att, M);

    // join before the edge phase
    cudaStreamWaitEvent(0, evJoin, 0);

    edge_pass1<<<(E + 255) / 256, 256>>>(E);

    // agg with programmatic stream serialization (PDL pair with edge_pass1)
    {
        long long aggThreads = (long long)E * 8;
        cudaLaunchConfig_t cfg = {};
        cfg.gridDim = dim3((unsigned)((aggThreads + 255) / 256));
        cfg.blockDim = dim3(256);
        cfg.dynamicSmemBytes = 0;
        cfg.stream = 0;
        cudaLaunchAttribute attr[1];
        attr[0].id = cudaLaunchAttributeProgrammaticStreamSerialization;
        attr[0].val.programmaticStreamSerializationAllowed = 1;
        cfg.attrs = attr;
        cfg.numAttrs = 1;
        cudaLaunchKernelEx(&cfg, agg_kernel, E, out);
    }
}